// round 3
// baseline (speedup 1.0000x reference)
#include <cuda_runtime.h>

// Scratch (no allocation allowed): per-node gate values, N = 100000 <= 131072.
#define MAX_NODES (1 << 17)
__device__ float g_gate[MAX_NODES];
__device__ int   g_is64;   // 1 if edge_index is int64, 0 if int32

// ---------------------------------------------------------------------------
// Kernel 1: gate[n] = sigmoid(dot(x[n,:], p) + b). Warp-per-row GEMV.
// Block 0 additionally detects the index width (int64 has zero high words;
// int32 odd words are random node ids -> P(all-zero) ~ 0). This runs
// concurrently with the other ~12.5k blocks, removing a serialized launch.
// Template D -> fully unrolled, 4 independent float4 loads per lane (MLP=4).
// ---------------------------------------------------------------------------
template <int D>
__global__ void gate_kernel_t(const float* __restrict__ x,
                              const float* __restrict__ p,
                              const float* __restrict__ bptr,
                              int N,
                              const int* __restrict__ ei32, int ei_words) {
    __shared__ float p_sh[D];
    int tid = threadIdx.x;
    #pragma unroll
    for (int i = tid; i < D; i += 256) p_sh[i] = p[i];

    // Index-width detection on block 0 (independent of gate math).
    if (blockIdx.x == 0) {
        __shared__ int nz;
        if (tid == 0) nz = 0;
        __syncthreads();
        int limit = 2048;
        if (limit * 2 > ei_words) limit = ei_words / 2;
        int c = 0;
        for (int i = tid; i < limit; i += 256)
            if (ei32[2 * i + 1] != 0) c = 1;
        if (c) atomicOr(&nz, 1);
        __syncthreads();
        if (tid == 0) g_is64 = (nz == 0) ? 1 : 0;
    } else {
        __syncthreads();  // matches p_sh fill visibility
    }
    __syncthreads();

    int warp = tid >> 5;
    int lane = tid & 31;
    int row  = blockIdx.x * 8 + warp;
    if (row >= N) return;

    const float4* xr = reinterpret_cast<const float4*>(x + (long long)row * D);
    const float4* pr = reinterpret_cast<const float4*>(p_sh);

    float sum = 0.0f;
    constexpr int NV = D >> 2;       // 128 for D=512
    #pragma unroll
    for (int j = 0; j < NV / 32; j++) {
        int i = lane + j * 32;
        float4 xv = xr[i];
        float4 pv = pr[i];
        sum = fmaf(xv.x, pv.x, sum);
        sum = fmaf(xv.y, pv.y, sum);
        sum = fmaf(xv.z, pv.z, sum);
        sum = fmaf(xv.w, pv.w, sum);
    }
    #pragma unroll
    for (int o = 16; o > 0; o >>= 1)
        sum += __shfl_down_sync(0xffffffffu, sum, o);

    if (lane == 0) {
        float v = sum + bptr[0];
        g_gate[row] = 1.0f / (1.0f + __expf(-v));
    }
}

// Generic-D fallback (also does detection in block 0).
__global__ void gate_kernel_g(const float* __restrict__ x,
                              const float* __restrict__ p,
                              const float* __restrict__ bptr,
                              int N, int D,
                              const int* __restrict__ ei32, int ei_words) {
    __shared__ float p_sh[1024];
    int tid = threadIdx.x;
    for (int i = tid; i < D; i += 256) p_sh[i] = p[i];

    if (blockIdx.x == 0) {
        __shared__ int nz;
        if (tid == 0) nz = 0;
        __syncthreads();
        int limit = 2048;
        if (limit * 2 > ei_words) limit = ei_words / 2;
        int c = 0;
        for (int i = tid; i < limit; i += 256)
            if (ei32[2 * i + 1] != 0) c = 1;
        if (c) atomicOr(&nz, 1);
        __syncthreads();
        if (tid == 0) g_is64 = (nz == 0) ? 1 : 0;
    } else {
        __syncthreads();
    }
    __syncthreads();

    int warp = tid >> 5;
    int lane = tid & 31;
    int row  = blockIdx.x * 8 + warp;
    if (row >= N) return;

    const float4* xr = reinterpret_cast<const float4*>(x + (long long)row * D);
    float sum = 0.0f;
    int nvec = D >> 2;
    for (int i = lane; i < nvec; i += 32) {
        float4 xv = xr[i];
        float4 pv = reinterpret_cast<const float4*>(p_sh)[i];
        sum = fmaf(xv.x, pv.x, sum);
        sum = fmaf(xv.y, pv.y, sum);
        sum = fmaf(xv.z, pv.z, sum);
        sum = fmaf(xv.w, pv.w, sum);
    }
    #pragma unroll
    for (int o = 16; o > 0; o >>= 1)
        sum += __shfl_down_sync(0xffffffffu, sum, o);

    if (lane == 0) {
        float v = sum + bptr[0];
        g_gate[row] = 1.0f / (1.0f + __expf(-v));
    }
}

// ---------------------------------------------------------------------------
// Kernel 2: adj[e] = attr[e] * gate[col[e]]; optional index passthrough as
// float (ids < 2^24, exact). 4 edges/thread, 16B memops. int64 index rows are
// loaded as int4 word-pairs; only the low 32-bit word is used (cheap I2F
// instead of I64->F32). Streaming hints keep the gate table resident in L2.
// ---------------------------------------------------------------------------
template <bool FULL>
__global__ void __launch_bounds__(256) edge_kernel(
        const void* __restrict__ eiv,
        const float* __restrict__ attr,
        float* __restrict__ out, int E) {
    const int is64 = g_is64;
    int g = blockIdx.x * blockDim.x + threadIdx.x;
    int e = g << 2;
    if (e >= E) return;

    if (e + 3 < E) {
        float4 av = __ldcs(reinterpret_cast<const float4*>(attr) + g);
        float4 adj, o0, o1;
        if (is64) {
            // int64 rows viewed as int words: int4 = {lo0, hi0, lo1, hi1}
            const int4* r1p = reinterpret_cast<const int4*>((const long long*)eiv + E);
            int4 b0 = __ldcs(r1p + 2 * g);
            int4 b1 = __ldcs(r1p + 2 * g + 1);
            adj.x = av.x * g_gate[b0.x];
            adj.y = av.y * g_gate[b0.z];
            adj.z = av.z * g_gate[b1.x];
            adj.w = av.w * g_gate[b1.z];
            if (FULL) {
                const int4* r0p = reinterpret_cast<const int4*>(eiv);
                int4 a0 = __ldcs(r0p + 2 * g);
                int4 a1 = __ldcs(r0p + 2 * g + 1);
                o0 = make_float4(__int2float_rn(a0.x), __int2float_rn(a0.z),
                                 __int2float_rn(a1.x), __int2float_rn(a1.z));
                o1 = make_float4(__int2float_rn(b0.x), __int2float_rn(b0.z),
                                 __int2float_rn(b1.x), __int2float_rn(b1.z));
            }
        } else {
            const int* ei = (const int*)eiv;
            int4 b = __ldcs(reinterpret_cast<const int4*>(ei + E) + g);
            adj.x = av.x * g_gate[b.x];
            adj.y = av.y * g_gate[b.y];
            adj.z = av.z * g_gate[b.z];
            adj.w = av.w * g_gate[b.w];
            if (FULL) {
                int4 a = __ldcs(reinterpret_cast<const int4*>(ei) + g);
                o0 = make_float4(__int2float_rn(a.x), __int2float_rn(a.y),
                                 __int2float_rn(a.z), __int2float_rn(a.w));
                o1 = make_float4(__int2float_rn(b.x), __int2float_rn(b.y),
                                 __int2float_rn(b.z), __int2float_rn(b.w));
            }
        }
        if (FULL) {
            __stcs(reinterpret_cast<float4*>(out) + g, o0);
            __stcs(reinterpret_cast<float4*>(out + E) + g, o1);
            __stcs(reinterpret_cast<float4*>(out + 2 * (size_t)E) + g, adj);
        } else {
            __stcs(reinterpret_cast<float4*>(out) + g, adj);
        }
    } else {
        for (int k = e; k < E; k++) {
            int c0, c1;
            if (is64) {
                const long long* ei = (const long long*)eiv;
                c0 = (int)ei[k];
                c1 = (int)ei[E + k];
            } else {
                const int* ei = (const int*)eiv;
                c0 = ei[k];
                c1 = ei[E + k];
            }
            float a = attr[k] * g_gate[c1];
            if (FULL) {
                out[k]                 = (float)c0;
                out[(size_t)E + k]     = (float)c1;
                out[2 * (size_t)E + k] = a;
            } else {
                out[k] = a;
            }
        }
    }
}

// ---------------------------------------------------------------------------
// Inputs (metadata order): x [N*D] f32, edge_index [2*E] (i32 or i64),
//                          edge_attr [E] f32, p [D] f32, b [1] f32
// ---------------------------------------------------------------------------
extern "C" void kernel_launch(void* const* d_in, const int* in_sizes, int n_in,
                              void* d_out, int out_size) {
    const float* x    = (const float*)d_in[0];
    const void*  ei   = d_in[1];
    const float* attr = (const float*)d_in[2];
    const float* p    = (const float*)d_in[3];
    const float* b    = (const float*)d_in[4];
    float* out = (float*)d_out;

    int ND = in_sizes[0];
    int E  = in_sizes[2];
    int D  = in_sizes[3];
    int N  = ND / D;

    // Kernel 1: per-node gates (+ index-width detection in block 0).
    int gblocks = (N + 7) / 8;
    if (D == 512) {
        gate_kernel_t<512><<<gblocks, 256>>>(x, p, b, N, (const int*)ei, in_sizes[1]);
    } else if (D == 256) {
        gate_kernel_t<256><<<gblocks, 256>>>(x, p, b, N, (const int*)ei, in_sizes[1]);
    } else if (D == 1024) {
        gate_kernel_t<1024><<<gblocks, 256>>>(x, p, b, N, (const int*)ei, in_sizes[1]);
    } else {
        gate_kernel_g<<<gblocks, 256>>>(x, p, b, N, D, (const int*)ei, in_sizes[1]);
    }

    // Kernel 2: edge scaling (+ optional index passthrough).
    int groups  = (E + 3) / 4;
    int eblocks = (groups + 255) / 256;
    if ((long long)out_size >= 3LL * E) {
        edge_kernel<true><<<eblocks, 256>>>(ei, attr, out, E);
    } else {
        edge_kernel<false><<<eblocks, 256>>>(ei, attr, out, E);
    }
}

// round 4
// speedup vs baseline: 1.2224x; 1.2224x over previous
#include <cuda_runtime.h>

// Scratch (no allocation allowed): per-node gate values, N = 100000 <= 131072.
#define MAX_NODES (1 << 17)
__device__ float g_gate[MAX_NODES];
__device__ int   g_is64;   // 1 if edge_index is int64, 0 if int32

// ---------------------------------------------------------------------------
// Kernel 1: gate[n] = sigmoid(dot(x[n,:], p) + b). Warp-per-row GEMV,
// p staged in shared, x read coalesced via float4 (runtime-D loop; this exact
// form measured 33us / ~6.2 TB/s in R2 — do not "improve" the load batching,
// front-batched MLP raises multi-CTA spread on B300).
// Block 0 additionally detects index width (int64 -> all high words zero)
// before its own row work; no extra syncs for other blocks.
// ---------------------------------------------------------------------------
__global__ void gate_kernel(const float* __restrict__ x,
                            const float* __restrict__ p,
                            const float* __restrict__ bptr,
                            int N, int D,
                            const int* __restrict__ ei32, int ei_words) {
    __shared__ float p_sh[1024];
    int tid = threadIdx.x;
    for (int i = tid; i < D; i += blockDim.x) p_sh[i] = p[i];

    if (blockIdx.x == 0) {
        // Detection: int32 odd words are random node ids, P(all zero) ~ 0.
        __shared__ int nz;
        if (tid == 0) nz = 0;
        __syncthreads();
        int limit = 2048;
        if (limit * 2 > ei_words) limit = ei_words / 2;
        int c = 0;
        for (int i = tid; i < limit; i += blockDim.x)
            if (ei32[2 * i + 1] != 0) c = 1;
        if (c) atomicOr(&nz, 1);
        __syncthreads();
        if (tid == 0) g_is64 = (nz == 0) ? 1 : 0;
    }
    __syncthreads();

    int warp = tid >> 5;
    int lane = tid & 31;
    int row  = blockIdx.x * (blockDim.x >> 5) + warp;
    if (row >= N) return;

    const float4* xr = reinterpret_cast<const float4*>(x + (long long)row * D);
    float sum = 0.0f;
    int nvec = D >> 2;
    for (int i = lane; i < nvec; i += 32) {
        float4 xv = xr[i];
        float4 pv = reinterpret_cast<const float4*>(p_sh)[i];
        sum = fmaf(xv.x, pv.x, sum);
        sum = fmaf(xv.y, pv.y, sum);
        sum = fmaf(xv.z, pv.z, sum);
        sum = fmaf(xv.w, pv.w, sum);
    }
    #pragma unroll
    for (int o = 16; o > 0; o >>= 1)
        sum += __shfl_down_sync(0xffffffffu, sum, o);

    if (lane == 0) {
        float v = sum + bptr[0];
        g_gate[row] = 1.0f / (1.0f + __expf(-v));
    }
}

// ---------------------------------------------------------------------------
// Kernel 2: adj[e] = attr[e] * gate[col[e]]; optional index passthrough as
// float (ids < 2^24, exact). 4 edges/thread, 16B vector memops, PLAIN loads
// and stores (no .cs hints — measured regression). int64 rows viewed as int4
// word-pairs so converts are cheap I2F on the low words.
// ---------------------------------------------------------------------------
template <bool FULL>
__global__ void __launch_bounds__(256) edge_kernel(
        const void* __restrict__ eiv,
        const float* __restrict__ attr,
        float* __restrict__ out, int E) {
    const int is64 = g_is64;
    int g = blockIdx.x * blockDim.x + threadIdx.x;
    int e = g << 2;
    if (e >= E) return;

    if (e + 3 < E) {
        float4 av = reinterpret_cast<const float4*>(attr)[g];
        float4 adj, o0, o1;
        if (is64) {
            // int64 rows viewed as int words: int4 = {lo0, hi0, lo1, hi1}
            const int4* r1p = reinterpret_cast<const int4*>((const long long*)eiv + E);
            int4 b0 = r1p[2 * g];
            int4 b1 = r1p[2 * g + 1];
            adj.x = av.x * g_gate[b0.x];
            adj.y = av.y * g_gate[b0.z];
            adj.z = av.z * g_gate[b1.x];
            adj.w = av.w * g_gate[b1.z];
            if (FULL) {
                const int4* r0p = reinterpret_cast<const int4*>(eiv);
                int4 a0 = r0p[2 * g];
                int4 a1 = r0p[2 * g + 1];
                o0 = make_float4(__int2float_rn(a0.x), __int2float_rn(a0.z),
                                 __int2float_rn(a1.x), __int2float_rn(a1.z));
                o1 = make_float4(__int2float_rn(b0.x), __int2float_rn(b0.z),
                                 __int2float_rn(b1.x), __int2float_rn(b1.z));
            }
        } else {
            const int* ei = (const int*)eiv;
            int4 b = reinterpret_cast<const int4*>(ei + E)[g];
            adj.x = av.x * g_gate[b.x];
            adj.y = av.y * g_gate[b.y];
            adj.z = av.z * g_gate[b.z];
            adj.w = av.w * g_gate[b.w];
            if (FULL) {
                int4 a = reinterpret_cast<const int4*>(ei)[g];
                o0 = make_float4(__int2float_rn(a.x), __int2float_rn(a.y),
                                 __int2float_rn(a.z), __int2float_rn(a.w));
                o1 = make_float4(__int2float_rn(b.x), __int2float_rn(b.y),
                                 __int2float_rn(b.z), __int2float_rn(b.w));
            }
        }
        if (FULL) {
            reinterpret_cast<float4*>(out)[g] = o0;
            reinterpret_cast<float4*>(out + E)[g] = o1;
            reinterpret_cast<float4*>(out + 2 * (size_t)E)[g] = adj;
        } else {
            reinterpret_cast<float4*>(out)[g] = adj;
        }
    } else {
        for (int k = e; k < E; k++) {
            int c0, c1;
            if (is64) {
                const long long* ei = (const long long*)eiv;
                c0 = (int)ei[k];
                c1 = (int)ei[E + k];
            } else {
                const int* ei = (const int*)eiv;
                c0 = ei[k];
                c1 = ei[E + k];
            }
            float a = attr[k] * g_gate[c1];
            if (FULL) {
                out[k]                 = (float)c0;
                out[(size_t)E + k]     = (float)c1;
                out[2 * (size_t)E + k] = a;
            } else {
                out[k] = a;
            }
        }
    }
}

// ---------------------------------------------------------------------------
// Inputs (metadata order): x [N*D] f32, edge_index [2*E] (i32 or i64),
//                          edge_attr [E] f32, p [D] f32, b [1] f32
// ---------------------------------------------------------------------------
extern "C" void kernel_launch(void* const* d_in, const int* in_sizes, int n_in,
                              void* d_out, int out_size) {
    const float* x    = (const float*)d_in[0];
    const void*  ei   = d_in[1];
    const float* attr = (const float*)d_in[2];
    const float* p    = (const float*)d_in[3];
    const float* b    = (const float*)d_in[4];
    float* out = (float*)d_out;

    int ND = in_sizes[0];
    int E  = in_sizes[2];
    int D  = in_sizes[3];
    int N  = ND / D;

    // Kernel 1: per-node gates (+ index-width detection in block 0).
    int rows_per_block = 256 / 32;
    int gblocks = (N + rows_per_block - 1) / rows_per_block;
    gate_kernel<<<gblocks, 256>>>(x, p, b, N, D, (const int*)ei, in_sizes[1]);

    // Kernel 2: edge scaling (+ optional index passthrough).
    int groups  = (E + 3) / 4;
    int eblocks = (groups + 255) / 256;
    if ((long long)out_size >= 3LL * E) {
        edge_kernel<true><<<eblocks, 256>>>(ei, attr, out, E);
    } else {
        edge_kernel<false><<<eblocks, 256>>>(ei, attr, out, E);
    }
}